// round 5
// baseline (speedup 1.0000x reference)
#include <cuda_runtime.h>
#include <math.h>

// Problem constants (B=4, C=256, H=W=256, heads=8, hd=32, WS=8 -> no padding)
#define BATCH   4
#define C_DIM   256
#define H_DIM   256
#define W_DIM   256
#define HW      (H_DIM * W_DIM)        // 65536
#define HEADS   8
#define HD      32
#define WSZ     8
#define NT      64                     // tokens per window
#define NWH     (H_DIM / WSZ)          // 32
#define NWW     (W_DIM / WSZ)          // 32

// Scratch: q, k, v (attention output overwrites q in-place, window-local)
__device__ float g_q[(size_t)BATCH * C_DIM * HW];
__device__ float g_k[(size_t)BATCH * C_DIM * HW];
__device__ float g_v[(size_t)BATCH * C_DIM * HW];

// ---------------------------------------------------------------------------
// Projection GEMM: Out[b][o][hw] = sum_c W[o][c] * X[b][c][hw]
// 128x128 block tile, BK=16, 256 threads, 8x8 per-thread micro-tile.
// grid = (HW/128 = 512, C/128 = 2, BATCH)
// ---------------------------------------------------------------------------
#define BM 128
#define BN 128
#define BK 16

__global__ __launch_bounds__(256, 2)
void proj_kernel(const float* __restrict__ Wt, const float* __restrict__ X,
                 float* __restrict__ Out) {
    __shared__ float Ws[BK][BM + 4];   // Ws[k][m] = W[m0+m][k0+k]; stride 132f=528B (16B mult)
    __shared__ float Xs[BK][BN];       // Xs[k][n] = X[k0+k][n0+n]

    const int b  = blockIdx.z;
    const int n0 = blockIdx.x * BN;
    const int m0 = blockIdx.y * BM;
    const float* Xb = X + (size_t)b * C_DIM * HW;
    float*       Ob = Out + (size_t)b * C_DIM * HW;

    const int t  = threadIdx.x;        // 0..255
    const int ty = t >> 4;             // 0..15  (m direction)
    const int tx = t & 15;             // 0..15  (n direction)

    float acc[8][8];
#pragma unroll
    for (int i = 0; i < 8; i++)
#pragma unroll
        for (int j = 0; j < 8; j++) acc[i][j] = 0.0f;

    for (int k0 = 0; k0 < C_DIM; k0 += BK) {
        // Load W tile (128 x 16), transposed store into Ws[k][m]
#pragma unroll
        for (int l = 0; l < 2; l++) {
            int idx = t + l * 256;                 // 0..511 float4 slots
            int m   = idx >> 2;                    // 0..127
            int k4  = (idx & 3) * 4;               // 0,4,8,12
            float4 w4 = *(const float4*)(Wt + (size_t)(m0 + m) * C_DIM + k0 + k4);
            Ws[k4 + 0][m] = w4.x;
            Ws[k4 + 1][m] = w4.y;
            Ws[k4 + 2][m] = w4.z;
            Ws[k4 + 3][m] = w4.w;
        }
        // Load X tile (16 x 128), n-contiguous float4
#pragma unroll
        for (int l = 0; l < 2; l++) {
            int idx = t + l * 256;                 // 0..511
            int k   = idx >> 5;                    // 0..15
            int n4  = (idx & 31) * 4;              // 0..124
            *(float4*)(&Xs[k][n4]) =
                *(const float4*)(Xb + (size_t)(k0 + k) * HW + n0 + n4);
        }
        __syncthreads();

#pragma unroll
        for (int k = 0; k < BK; k++) {
            float a[8], bb[8];
            float4 a0 = *(const float4*)(&Ws[k][ty * 8]);
            float4 a1 = *(const float4*)(&Ws[k][ty * 8 + 4]);
            float4 b0 = *(const float4*)(&Xs[k][tx * 8]);
            float4 b1 = *(const float4*)(&Xs[k][tx * 8 + 4]);
            a[0]=a0.x; a[1]=a0.y; a[2]=a0.z; a[3]=a0.w;
            a[4]=a1.x; a[5]=a1.y; a[6]=a1.z; a[7]=a1.w;
            bb[0]=b0.x; bb[1]=b0.y; bb[2]=b0.z; bb[3]=b0.w;
            bb[4]=b1.x; bb[5]=b1.y; bb[6]=b1.z; bb[7]=b1.w;
#pragma unroll
            for (int i = 0; i < 8; i++)
#pragma unroll
                for (int j = 0; j < 8; j++)
                    acc[i][j] += a[i] * bb[j];
        }
        __syncthreads();
    }

#pragma unroll
    for (int i = 0; i < 8; i++) {
        int m = m0 + ty * 8 + i;
#pragma unroll
        for (int j = 0; j < 8; j += 4) {
            float4 v4 = make_float4(acc[i][j], acc[i][j+1], acc[i][j+2], acc[i][j+3]);
            *(float4*)(Ob + (size_t)m * HW + n0 + tx * 8 + j) = v4;
        }
    }
}

// ---------------------------------------------------------------------------
// Window attention: one block per (window, head). 256 threads.
// S = Q^T K * scale -> softmax over j -> O = V P^T, written back over Q.
// grid = (NWH*NWW = 1024, HEADS = 8, BATCH = 4)
// ---------------------------------------------------------------------------
#define PT_PAD 4   // row stride NT+4 = 68 floats = 272B: 16B-aligned for float4

__global__ __launch_bounds__(256)
void attn_kernel(const float* __restrict__ Q, const float* __restrict__ K,
                 const float* __restrict__ V, float* __restrict__ O) {
    __shared__ float qs[HD][NT];        // [c][tok]
    __shared__ float ks[HD][NT];
    __shared__ float vs[HD][NT];
    __shared__ float pT[NT][NT + PT_PAD]; // pT[j][i] = S[i][j] (then softmaxed P)

    const int win  = blockIdx.x;
    const int wh   = win >> 5;          // /32
    const int ww   = win & 31;
    const int head = blockIdx.y;
    const int b    = blockIdx.z;
    const int t    = threadIdx.x;

    const size_t base = ((size_t)(b * C_DIM + head * HD)) * HW
                      + (size_t)(wh * WSZ) * W_DIM + (size_t)(ww * WSZ);

    // ---- Load Q,K,V window tiles: (c, tok) <- gmem, tok = r*8 + col ----
#pragma unroll
    for (int l = 0; l < 2; l++) {
        int idx4 = t + l * 256;          // 0..511 float4 slots
        int c    = idx4 >> 4;            // 0..31
        int tok  = (idx4 & 15) * 4;      // 0..60
        int r    = tok >> 3;
        int col  = tok & 7;
        size_t g = base + (size_t)c * HW + (size_t)r * W_DIM + col;
        *(float4*)(&qs[c][tok]) = *(const float4*)(Q + g);
        *(float4*)(&ks[c][tok]) = *(const float4*)(K + g);
        *(float4*)(&vs[c][tok]) = *(const float4*)(V + g);
    }
    __syncthreads();

    // ---- S phase: 4x4 tile per thread, store transposed into pT ----
    {
        const int ti = (t >> 4) * 4;     // 0..60
        const int tj = (t & 15) * 4;     // 0..60
        float sacc[4][4];
#pragma unroll
        for (int i = 0; i < 4; i++)
#pragma unroll
            for (int j = 0; j < 4; j++) sacc[i][j] = 0.0f;

#pragma unroll
        for (int c = 0; c < HD; c++) {
            float4 qa = *(const float4*)(&qs[c][ti]);
            float4 kb = *(const float4*)(&ks[c][tj]);
            float a[4] = {qa.x, qa.y, qa.z, qa.w};
            float bb[4] = {kb.x, kb.y, kb.z, kb.w};
#pragma unroll
            for (int i = 0; i < 4; i++)
#pragma unroll
                for (int j = 0; j < 4; j++)
                    sacc[i][j] += a[i] * bb[j];
        }
#pragma unroll
        for (int i = 0; i < 4; i++)
#pragma unroll
            for (int j = 0; j < 4; j++)
                pT[tj + j][ti + i] = sacc[i][j];
    }
    __syncthreads();

    // ---- Softmax over j for each row i. 4 threads per row, 16 j each. ----
    {
        const float scale = 1.0f / sqrtf((float)HD);
        const int r = t >> 2;            // row 0..63
        const int q = t & 3;             // quarter
        float e[16];
        float m = -1e30f;
#pragma unroll
        for (int s = 0; s < 16; s++) {
            float xv = pT[q * 16 + s][r] * scale;
            e[s] = xv;
            m = fmaxf(m, xv);
        }
        m = fmaxf(m, __shfl_xor_sync(0xffffffffu, m, 1));
        m = fmaxf(m, __shfl_xor_sync(0xffffffffu, m, 2));
        float sum = 0.0f;
#pragma unroll
        for (int s = 0; s < 16; s++) {
            e[s] = __expf(e[s] - m);
            sum += e[s];
        }
        sum += __shfl_xor_sync(0xffffffffu, sum, 1);
        sum += __shfl_xor_sync(0xffffffffu, sum, 2);
        float inv = 1.0f / sum;
#pragma unroll
        for (int s = 0; s < 16; s++)
            pT[q * 16 + s][r] = e[s] * inv;
    }
    __syncthreads();

    // ---- O phase: O[c][i] = sum_j P[i][j] * V[c][j]; 2(c) x 4(i) tile ----
    {
        const int tc  = (t >> 4) * 2;    // 0..30
        const int ti2 = (t & 15) * 4;    // 0..60
        float oacc[2][4];
#pragma unroll
        for (int cc = 0; cc < 2; cc++)
#pragma unroll
            for (int i = 0; i < 4; i++) oacc[cc][i] = 0.0f;

#pragma unroll 4
        for (int j = 0; j < NT; j++) {
            float4 p4 = *(const float4*)(&pT[j][ti2]);
            float p[4] = {p4.x, p4.y, p4.z, p4.w};
            float v0 = vs[tc + 0][j];
            float v1 = vs[tc + 1][j];
#pragma unroll
            for (int i = 0; i < 4; i++) {
                oacc[0][i] += v0 * p[i];
                oacc[1][i] += v1 * p[i];
            }
        }
#pragma unroll
        for (int cc = 0; cc < 2; cc++) {
#pragma unroll
            for (int i = 0; i < 4; i++) {
                int tok = ti2 + i;
                int r   = tok >> 3;
                int col = tok & 7;
                O[base + (size_t)(tc + cc) * HW + (size_t)r * W_DIM + col] = oacc[cc][i];
            }
        }
    }
}

// ---------------------------------------------------------------------------
extern "C" void kernel_launch(void* const* d_in, const int* in_sizes, int n_in,
                              void* d_out, int out_size) {
    const float* x  = (const float*)d_in[0];
    const float* Wq = (const float*)d_in[1];
    const float* Wk = (const float*)d_in[2];
    const float* Wv = (const float*)d_in[3];
    const float* Wo = (const float*)d_in[4];
    float* out = (float*)d_out;

    void *pq, *pk, *pv;
    cudaGetSymbolAddress(&pq, g_q);
    cudaGetSymbolAddress(&pk, g_k);
    cudaGetSymbolAddress(&pv, g_v);
    float* q = (float*)pq;
    float* k = (float*)pk;
    float* v = (float*)pv;

    dim3 gproj(HW / BN, C_DIM / BM, BATCH);   // (512, 2, 4)
    proj_kernel<<<gproj, 256>>>(Wq, x, q);
    proj_kernel<<<gproj, 256>>>(Wk, x, k);
    proj_kernel<<<gproj, 256>>>(Wv, x, v);

    dim3 gattn(NWH * NWW, HEADS, BATCH);      // (1024, 8, 4)
    attn_kernel<<<gattn, 256>>>(q, k, v, /*O overwrites q in-place*/ q);

    proj_kernel<<<gproj, 256>>>(Wo, q, out);
}

// round 7
// speedup vs baseline: 1.0251x; 1.0251x over previous
#include <cuda_runtime.h>
#include <math.h>

// Problem constants (B=4, C=256, H=W=256, heads=8, hd=32, WS=8 -> no padding)
#define BATCH   4
#define C_DIM   256
#define H_DIM   256
#define W_DIM   256
#define HW      (H_DIM * W_DIM)        // 65536
#define HEADS   8
#define HD      32
#define WSZ     8
#define NT      64                     // tokens per window
#define NWH     (H_DIM / WSZ)          // 32
#define NWW     (W_DIM / WSZ)          // 32

// Packed fp32x2 FMA (SASS FFMA2): d = a*b + c per 32-bit lane of 64-bit regs.
#define FMA_F32X2(d, a, b, c) \
    asm("fma.rn.f32x2 %0, %1, %2, %3;" : "=l"(d) : "l"(a), "l"(b), "l"(c))
#define DUP_F32X2(d, s) \
    asm("mov.b64 %0, {%1, %1};" : "=l"(d) : "r"(s))
#define UNPK_F32X2(lo, hi, s) \
    asm("mov.b64 {%0, %1}, %2;" : "=r"(lo), "=r"(hi) : "l"(s))

// Scratch: q, k, v (attention output overwrites q in-place, window-local)
__device__ float g_q[(size_t)BATCH * C_DIM * HW];
__device__ float g_k[(size_t)BATCH * C_DIM * HW];
__device__ float g_v[(size_t)BATCH * C_DIM * HW];

// ---------------------------------------------------------------------------
// Projection GEMM: Out[b][o][hw] = sum_c W[o][c] * X[b][c][hw]
// 128x128 block tile, BK=16, 256 threads, 8x8 per-thread micro-tile,
// accumulated as 8x4 packed f32x2 pairs (pair over the n/j dimension).
// grid = (HW/128 = 512, C/128 = 2, BATCH)
// ---------------------------------------------------------------------------
#define BM 128
#define BN 128
#define BK 16

__global__ __launch_bounds__(256, 2)
void proj_kernel(const float* __restrict__ Wt, const float* __restrict__ X,
                 float* __restrict__ Out) {
    __shared__ float Ws[BK][BM + 4];   // Ws[k][m] = W[m0+m][k0+k]; stride 528B (16B mult)
    __shared__ float Xs[BK][BN];       // Xs[k][n] = X[k0+k][n0+n]

    const int b  = blockIdx.z;
    const int n0 = blockIdx.x * BN;
    const int m0 = blockIdx.y * BM;
    const float* Xb = X + (size_t)b * C_DIM * HW;
    float*       Ob = Out + (size_t)b * C_DIM * HW;

    const int t  = threadIdx.x;        // 0..255
    const int ty = t >> 4;             // 0..15  (m direction)
    const int tx = t & 15;             // 0..15  (n direction)

    unsigned long long accp[8][4];     // [i][jpair]; each packs (j, j+1)
#pragma unroll
    for (int i = 0; i < 8; i++)
#pragma unroll
        for (int jp = 0; jp < 4; jp++) accp[i][jp] = 0ull;

    for (int k0 = 0; k0 < C_DIM; k0 += BK) {
        // Load W tile (128 x 16), transposed store into Ws[k][m]
#pragma unroll
        for (int l = 0; l < 2; l++) {
            int idx = t + l * 256;                 // 0..511 float4 slots
            int m   = idx >> 2;                    // 0..127
            int k4  = (idx & 3) * 4;               // 0,4,8,12
            float4 w4 = *(const float4*)(Wt + (size_t)(m0 + m) * C_DIM + k0 + k4);
            Ws[k4 + 0][m] = w4.x;
            Ws[k4 + 1][m] = w4.y;
            Ws[k4 + 2][m] = w4.z;
            Ws[k4 + 3][m] = w4.w;
        }
        // Load X tile (16 x 128), n-contiguous float4
#pragma unroll
        for (int l = 0; l < 2; l++) {
            int idx = t + l * 256;                 // 0..511
            int k   = idx >> 5;                    // 0..15
            int n4  = (idx & 31) * 4;              // 0..124
            *(float4*)(&Xs[k][n4]) =
                *(const float4*)(Xb + (size_t)(k0 + k) * HW + n0 + n4);
        }
        __syncthreads();

#pragma unroll
        for (int k = 0; k < BK; k++) {
            // a values (m tile) -> duplicated f32x2
            float4 a0 = *(const float4*)(&Ws[k][ty * 8]);
            float4 a1 = *(const float4*)(&Ws[k][ty * 8 + 4]);
            float av[8] = {a0.x, a0.y, a0.z, a0.w, a1.x, a1.y, a1.z, a1.w};
            unsigned long long ad[8];
#pragma unroll
            for (int i = 0; i < 8; i++) DUP_F32X2(ad[i], __float_as_int(av[i]));

            // b pairs (n tile): reinterpret 2x float4 as 4x (f32,f32) packs
            const unsigned long long* bq0 =
                (const unsigned long long*)(&Xs[k][tx * 8]);
            unsigned long long bp0 = bq0[0];
            unsigned long long bp1 = bq0[1];
            unsigned long long bp2 = bq0[2];
            unsigned long long bp3 = bq0[3];

#pragma unroll
            for (int i = 0; i < 8; i++) {
                FMA_F32X2(accp[i][0], ad[i], bp0, accp[i][0]);
                FMA_F32X2(accp[i][1], ad[i], bp1, accp[i][1]);
                FMA_F32X2(accp[i][2], ad[i], bp2, accp[i][2]);
                FMA_F32X2(accp[i][3], ad[i], bp3, accp[i][3]);
            }
        }
        __syncthreads();
    }

#pragma unroll
    for (int i = 0; i < 8; i++) {
        int m = m0 + ty * 8 + i;
        unsigned lo0, hi0, lo1, hi1;
#pragma unroll
        for (int jp = 0; jp < 4; jp += 2) {
            UNPK_F32X2(lo0, hi0, accp[i][jp]);
            UNPK_F32X2(lo1, hi1, accp[i][jp + 1]);
            float4 v4 = make_float4(__int_as_float(lo0), __int_as_float(hi0),
                                    __int_as_float(lo1), __int_as_float(hi1));
            *(float4*)(Ob + (size_t)m * HW + n0 + tx * 8 + jp * 2) = v4;
        }
    }
}

// ---------------------------------------------------------------------------
// Window attention: one block per (window, head). 256 threads.
// S = Q^T K * scale -> softmax over j -> O = V P^T, written back over Q.
// grid = (NWH*NWW = 1024, HEADS = 8, BATCH = 4)
// ---------------------------------------------------------------------------
#define PT_PAD 4   // row stride NT+4 = 68 floats = 272B: 16B-aligned for float4

__global__ __launch_bounds__(256)
void attn_kernel(const float* __restrict__ Q, const float* __restrict__ K,
                 const float* __restrict__ V, float* __restrict__ O) {
    __shared__ float qs[HD][NT];        // [c][tok]
    __shared__ float ks[HD][NT];
    __shared__ float vs[HD][NT];
    __shared__ float pT[NT][NT + PT_PAD]; // pT[j][i] = S[i][j] (then softmaxed P)

    const int win  = blockIdx.x;
    const int wh   = win >> 5;          // /32
    const int ww   = win & 31;
    const int head = blockIdx.y;
    const int b    = blockIdx.z;
    const int t    = threadIdx.x;

    const size_t base = ((size_t)(b * C_DIM + head * HD)) * HW
                      + (size_t)(wh * WSZ) * W_DIM + (size_t)(ww * WSZ);

    // ---- Load Q,K,V window tiles: (c, tok) <- gmem, tok = r*8 + col ----
#pragma unroll
    for (int l = 0; l < 2; l++) {
        int idx4 = t + l * 256;          // 0..511 float4 slots
        int c    = idx4 >> 4;            // 0..31
        int tok  = (idx4 & 15) * 4;      // 0..60
        int r    = tok >> 3;
        int col  = tok & 7;
        size_t g = base + (size_t)c * HW + (size_t)r * W_DIM + col;
        *(float4*)(&qs[c][tok]) = *(const float4*)(Q + g);
        *(float4*)(&ks[c][tok]) = *(const float4*)(K + g);
        *(float4*)(&vs[c][tok]) = *(const float4*)(V + g);
    }
    __syncthreads();

    // ---- S phase: 4x4 tile per thread; write transposed via float4 rows ----
    {
        const int ti = (t >> 4) * 4;     // 0..60
        const int tj = (t & 15) * 4;     // 0..60
        float sacc[4][4];
#pragma unroll
        for (int i = 0; i < 4; i++)
#pragma unroll
            for (int j = 0; j < 4; j++) sacc[i][j] = 0.0f;

#pragma unroll
        for (int c = 0; c < HD; c++) {
            float4 qa = *(const float4*)(&qs[c][ti]);
            float4 kb = *(const float4*)(&ks[c][tj]);
            float a[4] = {qa.x, qa.y, qa.z, qa.w};
            float bb[4] = {kb.x, kb.y, kb.z, kb.w};
#pragma unroll
            for (int i = 0; i < 4; i++)
#pragma unroll
                for (int j = 0; j < 4; j++)
                    sacc[i][j] += a[i] * bb[j];
        }
        // Thread owns pT rows tj..tj+3, columns ti..ti+3 -> 4x STS.128
#pragma unroll
        for (int j = 0; j < 4; j++) {
            float4 row = make_float4(sacc[0][j], sacc[1][j], sacc[2][j], sacc[3][j]);
            *(float4*)(&pT[tj + j][ti]) = row;
        }
    }
    __syncthreads();

    // ---- Softmax over j for each row i. 4 threads per row. ----
    // j = s*4 + q: bank = s*16 + q*4 + r (mod 32) -> conflict-free.
    {
        const float scale = 1.0f / sqrtf((float)HD);
        const int r = t >> 2;            // row 0..63
        const int q = t & 3;             // quarter
        float e[16];
        float m = -1e30f;
#pragma unroll
        for (int s = 0; s < 16; s++) {
            float xv = pT[s * 4 + q][r] * scale;
            e[s] = xv;
            m = fmaxf(m, xv);
        }
        m = fmaxf(m, __shfl_xor_sync(0xffffffffu, m, 1));
        m = fmaxf(m, __shfl_xor_sync(0xffffffffu, m, 2));
        float sum = 0.0f;
#pragma unroll
        for (int s = 0; s < 16; s++) {
            e[s] = __expf(e[s] - m);
            sum += e[s];
        }
        sum += __shfl_xor_sync(0xffffffffu, sum, 1);
        sum += __shfl_xor_sync(0xffffffffu, sum, 2);
        float inv = 1.0f / sum;
#pragma unroll
        for (int s = 0; s < 16; s++)
            pT[s * 4 + q][r] = e[s] * inv;
    }
    __syncthreads();

    // ---- O phase: O[c][i] = sum_j P[i][j] * V[c][j]; 2(c) x 4(i) tile,
    //      4-j unrolled with vectorized vs loads ----
    {
        const int tc  = (t >> 4) * 2;    // 0..30
        const int ti2 = (t & 15) * 4;    // 0..60
        float oacc[2][4];
#pragma unroll
        for (int cc = 0; cc < 2; cc++)
#pragma unroll
            for (int i = 0; i < 4; i++) oacc[cc][i] = 0.0f;

#pragma unroll 4
        for (int j0 = 0; j0 < NT; j0 += 4) {
            float4 v0 = *(const float4*)(&vs[tc + 0][j0]);
            float4 v1 = *(const float4*)(&vs[tc + 1][j0]);
            float va0[4] = {v0.x, v0.y, v0.z, v0.w};
            float va1[4] = {v1.x, v1.y, v1.z, v1.w};
#pragma unroll
            for (int jj = 0; jj < 4; jj++) {
                float4 p4 = *(const float4*)(&pT[j0 + jj][ti2]);
                float p[4] = {p4.x, p4.y, p4.z, p4.w};
#pragma unroll
                for (int i = 0; i < 4; i++) {
                    oacc[0][i] += va0[jj] * p[i];
                    oacc[1][i] += va1[jj] * p[i];
                }
            }
        }
#pragma unroll
        for (int cc = 0; cc < 2; cc++) {
#pragma unroll
            for (int i = 0; i < 4; i++) {
                int tok = ti2 + i;
                int r   = tok >> 3;
                int col = tok & 7;
                O[base + (size_t)(tc + cc) * HW + (size_t)r * W_DIM + col] = oacc[cc][i];
            }
        }
    }
}

// ---------------------------------------------------------------------------
extern "C" void kernel_launch(void* const* d_in, const int* in_sizes, int n_in,
                              void* d_out, int out_size) {
    const float* x  = (const float*)d_in[0];
    const float* Wq = (const float*)d_in[1];
    const float* Wk = (const float*)d_in[2];
    const float* Wv = (const float*)d_in[3];
    const float* Wo = (const float*)d_in[4];
    float* out = (float*)d_out;

    void *pq, *pk, *pv;
    cudaGetSymbolAddress(&pq, g_q);
    cudaGetSymbolAddress(&pk, g_k);
    cudaGetSymbolAddress(&pv, g_v);
    float* q = (float*)pq;
    float* k = (float*)pk;
    float* v = (float*)pv;

    dim3 gproj(HW / BN, C_DIM / BM, BATCH);   // (512, 2, 4)
    proj_kernel<<<gproj, 256>>>(Wq, x, q);
    proj_kernel<<<gproj, 256>>>(Wk, x, k);
    proj_kernel<<<gproj, 256>>>(Wv, x, v);

    dim3 gattn(NWH * NWW, HEADS, BATCH);      // (1024, 8, 4)
    attn_kernel<<<gattn, 256>>>(q, k, v, /*O overwrites q in-place*/ q);

    proj_kernel<<<gproj, 256>>>(Wo, q, out);
}

// round 10
// speedup vs baseline: 1.2421x; 1.2118x over previous
#include <cuda_runtime.h>
#include <cuda_bf16.h>
#include <math.h>
#include <stdint.h>

// Problem constants (B=4, C=256, H=W=256, heads=8, hd=32, WS=8 -> no padding)
#define BATCH   4
#define C_DIM   256
#define H_DIM   256
#define W_DIM   256
#define HW      (H_DIM * W_DIM)        // 65536
#define HEADS   8
#define HD      32
#define WSZ     8
#define NT      64
#define NWH     (H_DIM / WSZ)
#define NWW     (W_DIM / WSZ)

// Scratch: q, k, v (attention output overwrites q in-place, window-local)
__device__ float g_q[(size_t)BATCH * C_DIM * HW];
__device__ float g_k[(size_t)BATCH * C_DIM * HW];
__device__ float g_v[(size_t)BATCH * C_DIM * HW];

// ============================ helpers ======================================
__device__ __forceinline__ uint32_t smem_u32(const void* p) {
    uint32_t a;
    asm("{ .reg .u64 t; cvta.to.shared.u64 t, %1; cvt.u32.u64 %0, t; }"
        : "=r"(a) : "l"(p));
    return a;
}
__device__ __forceinline__ void ldsm4(uint32_t* r, uint32_t addr) {
    asm volatile("ldmatrix.sync.aligned.m8n8.x4.shared.b16 {%0,%1,%2,%3}, [%4];"
                 : "=r"(r[0]), "=r"(r[1]), "=r"(r[2]), "=r"(r[3]) : "r"(addr));
}
__device__ __forceinline__ void mma16816(float* c, const uint32_t* a,
                                         const uint32_t* b) {
    asm volatile(
        "mma.sync.aligned.m16n8k16.row.col.f32.bf16.bf16.f32 "
        "{%0,%1,%2,%3},{%4,%5,%6,%7},{%8,%9},{%0,%1,%2,%3};"
        : "+f"(c[0]), "+f"(c[1]), "+f"(c[2]), "+f"(c[3])
        : "r"(a[0]), "r"(a[1]), "r"(a[2]), "r"(a[3]), "r"(b[0]), "r"(b[1]));
}
__device__ __forceinline__ float bfl(float a) {
    return __bfloat162float(__float2bfloat16_rn(a));
}
__device__ __forceinline__ uint32_t pk(float a, float b) {
    uint32_t sa = __bfloat16_as_ushort(__float2bfloat16_rn(a));
    uint32_t sb = __bfloat16_as_ushort(__float2bfloat16_rn(b));
    return sa | (sb << 16);
}

// ---------------------------------------------------------------------------
// Tensor-core projection GEMM (mma.sync bf16, 2-term split hi/lo):
//   Out[b][m][n] = sum_k W[m][k] * X[b][k][n]
// BM=128, BN=128, BK=32; 8 warps (2m x 4n), warp tile 64x32.
// A (W): smem [m][k] k-contig;  B (X): smem [n][k] k-contig (transposed fill).
// Row stride 80B -> ldmatrix conflict-free (20*r mod 32 all-distinct groups).
// grid = (HW/128 = 512, C/128 = 2, BATCH)
// ---------------------------------------------------------------------------
#define ROWB 80          // bytes per smem row (32 bf16 = 64B data + 16B pad)

__global__ __launch_bounds__(256, 1)
void proj_mma(const float* __restrict__ Wt, const float* __restrict__ X,
              float* __restrict__ Out) {
    __shared__ __align__(16) char As_hi[128 * ROWB];
    __shared__ __align__(16) char As_lo[128 * ROWB];
    __shared__ __align__(16) char Bs_hi[128 * ROWB];
    __shared__ __align__(16) char Bs_lo[128 * ROWB];

    const int t   = threadIdx.x;
    const int l   = t & 31;
    const int wid = t >> 5;
    const int b   = blockIdx.z;
    const int n0  = blockIdx.x * 128;
    const int m0  = blockIdx.y * 128;
    const float* Xb = X + (size_t)b * C_DIM * HW;
    float*       Ob = Out + (size_t)b * C_DIM * HW;

    const int wm = (wid >> 2) * 64;    // warp m offset: 0 or 64
    const int wn = (wid & 3) * 32;     // warp n offset: 0,32,64,96

    const uint32_t asHi = smem_u32(As_hi), asLo = smem_u32(As_lo);
    const uint32_t bsHi = smem_u32(Bs_hi), bsLo = smem_u32(Bs_lo);

    // Per-lane ldmatrix address components.
    // A x4, matrix q=l>>3: row = m + (l&7) + (q&1)*8 ; k += (q>>1)*8
    const uint32_t aRow = (uint32_t)((l & 7) + ((l >> 3) & 1) * 8);
    const uint32_t aKof = (uint32_t)(((l >> 4) & 1) * 8);
    // B x4, matrix q=l>>3: row(n) = n + (l&7) + (q>>1)*8 ; k += (q&1)*8
    const uint32_t bRow = (uint32_t)((l & 7) + ((l >> 4) & 1) * 8);
    const uint32_t bKof = (uint32_t)(((l >> 3) & 1) * 8);

    float acc[4][4][4];
#pragma unroll
    for (int mi = 0; mi < 4; mi++)
#pragma unroll
        for (int ni = 0; ni < 4; ni++)
#pragma unroll
            for (int r = 0; r < 4; r++) acc[mi][ni][r] = 0.0f;

    for (int k0 = 0; k0 < C_DIM; k0 += 32) {
        __syncthreads();
        // ---- A fill: W[m0+m][k0..k0+31] -> As_hi/As_lo [m][k] ----
#pragma unroll
        for (int u = 0; u < 4; u++) {
            int idx = t * 4 + u;               // 0..1023
            int m   = idx >> 3;                // 0..127
            int kq  = idx & 7;                 // float4 group
            float4 w4 = *(const float4*)(Wt + (size_t)(m0 + m) * C_DIM + k0 + kq * 4);
            uint32_t off = (uint32_t)(m * ROWB + kq * 8);
            *(uint2*)(As_hi + off) = make_uint2(pk(w4.x, w4.y), pk(w4.z, w4.w));
            *(uint2*)(As_lo + off) =
                make_uint2(pk(w4.x - bfl(w4.x), w4.y - bfl(w4.y)),
                           pk(w4.z - bfl(w4.z), w4.w - bfl(w4.w)));
        }
        // ---- B fill (transpose): X[k0+2kp(+1)][n0+n] -> Bs[n][kpair] ----
#pragma unroll
        for (int i = 0; i < 8; i++) {
            int idx = t + i * 256;             // 0..2047
            int n   = idx & 127;
            int kp  = idx >> 7;                // 0..15
            const float* xp = Xb + (size_t)(k0 + 2 * kp) * HW + n0 + n;
            float x0 = xp[0];
            float x1 = xp[HW];
            uint32_t off = (uint32_t)(n * ROWB + kp * 4);
            *(uint32_t*)(Bs_hi + off) = pk(x0, x1);
            *(uint32_t*)(Bs_lo + off) = pk(x0 - bfl(x0), x1 - bfl(x1));
        }
        __syncthreads();

        // ---- Compute: 2 k-steps of 16 ----
#pragma unroll
        for (int ks = 0; ks < 2; ks++) {
            const uint32_t kk = (uint32_t)(ks * 16);
            uint32_t a_hi[4][4], a_lo[4][4], b_hi[4][2], b_lo[4][2];
#pragma unroll
            for (int mi = 0; mi < 4; mi++) {
                uint32_t ao = (uint32_t)((wm + mi * 16 + aRow) * ROWB)
                            + (kk + aKof) * 2;
                ldsm4(a_hi[mi], asHi + ao);
                ldsm4(a_lo[mi], asLo + ao);
            }
#pragma unroll
            for (int nj = 0; nj < 2; nj++) {
                uint32_t bo = (uint32_t)((wn + nj * 16 + bRow) * ROWB)
                            + (kk + bKof) * 2;
                uint32_t rh[4], rl[4];
                ldsm4(rh, bsHi + bo);
                ldsm4(rl, bsLo + bo);
                b_hi[nj * 2 + 0][0] = rh[0]; b_hi[nj * 2 + 0][1] = rh[1];
                b_hi[nj * 2 + 1][0] = rh[2]; b_hi[nj * 2 + 1][1] = rh[3];
                b_lo[nj * 2 + 0][0] = rl[0]; b_lo[nj * 2 + 0][1] = rl[1];
                b_lo[nj * 2 + 1][0] = rl[2]; b_lo[nj * 2 + 1][1] = rl[3];
            }
#pragma unroll
            for (int mi = 0; mi < 4; mi++)
#pragma unroll
                for (int ni = 0; ni < 4; ni++) {
                    mma16816(acc[mi][ni], a_hi[mi], b_hi[ni]);
                    mma16816(acc[mi][ni], a_hi[mi], b_lo[ni]);
                    mma16816(acc[mi][ni], a_lo[mi], b_hi[ni]);
                }
        }
    }

    // ---- Epilogue: direct float2 stores (c0,c1)->(m, 2t), (c2,c3)->(m+8) ----
    const int g  = l >> 2;
    const int tt = l & 3;
#pragma unroll
    for (int mi = 0; mi < 4; mi++) {
#pragma unroll
        for (int ni = 0; ni < 4; ni++) {
            const float* c = acc[mi][ni];
            int m = m0 + wm + mi * 16 + g;
            int n = n0 + wn + ni * 8 + tt * 2;
            *(float2*)(Ob + (size_t)m * HW + n)       = make_float2(c[0], c[1]);
            *(float2*)(Ob + (size_t)(m + 8) * HW + n) = make_float2(c[2], c[3]);
        }
    }
}

// ---------------------------------------------------------------------------
// Window attention (unchanged, measured 852us): one block per (window, head).
// ---------------------------------------------------------------------------
#define PT_PAD 4

__global__ __launch_bounds__(256)
void attn_kernel(const float* __restrict__ Q, const float* __restrict__ K,
                 const float* __restrict__ V, float* __restrict__ O) {
    __shared__ float qs[HD][NT];
    __shared__ float ks[HD][NT];
    __shared__ float vs[HD][NT];
    __shared__ float pT[NT][NT + PT_PAD];

    const int win  = blockIdx.x;
    const int wh   = win >> 5;
    const int ww   = win & 31;
    const int head = blockIdx.y;
    const int b    = blockIdx.z;
    const int t    = threadIdx.x;

    const size_t base = ((size_t)(b * C_DIM + head * HD)) * HW
                      + (size_t)(wh * WSZ) * W_DIM + (size_t)(ww * WSZ);

#pragma unroll
    for (int l = 0; l < 2; l++) {
        int idx4 = t + l * 256;
        int c    = idx4 >> 4;
        int tok  = (idx4 & 15) * 4;
        int r    = tok >> 3;
        int col  = tok & 7;
        size_t g = base + (size_t)c * HW + (size_t)r * W_DIM + col;
        *(float4*)(&qs[c][tok]) = *(const float4*)(Q + g);
        *(float4*)(&ks[c][tok]) = *(const float4*)(K + g);
        *(float4*)(&vs[c][tok]) = *(const float4*)(V + g);
    }
    __syncthreads();

    {
        const int ti = (t >> 4) * 4;
        const int tj = (t & 15) * 4;
        float sacc[4][4];
#pragma unroll
        for (int i = 0; i < 4; i++)
#pragma unroll
            for (int j = 0; j < 4; j++) sacc[i][j] = 0.0f;

#pragma unroll
        for (int c = 0; c < HD; c++) {
            float4 qa = *(const float4*)(&qs[c][ti]);
            float4 kb = *(const float4*)(&ks[c][tj]);
            float a[4] = {qa.x, qa.y, qa.z, qa.w};
            float bb[4] = {kb.x, kb.y, kb.z, kb.w};
#pragma unroll
            for (int i = 0; i < 4; i++)
#pragma unroll
                for (int j = 0; j < 4; j++)
                    sacc[i][j] += a[i] * bb[j];
        }
#pragma unroll
        for (int j = 0; j < 4; j++) {
            float4 row = make_float4(sacc[0][j], sacc[1][j], sacc[2][j], sacc[3][j]);
            *(float4*)(&pT[tj + j][ti]) = row;
        }
    }
    __syncthreads();

    {
        const float scale = 1.0f / sqrtf((float)HD);
        const int r = t >> 2;
        const int q = t & 3;
        float e[16];
        float m = -1e30f;
#pragma unroll
        for (int s = 0; s < 16; s++) {
            float xv = pT[s * 4 + q][r] * scale;
            e[s] = xv;
            m = fmaxf(m, xv);
        }
        m = fmaxf(m, __shfl_xor_sync(0xffffffffu, m, 1));
        m = fmaxf(m, __shfl_xor_sync(0xffffffffu, m, 2));
        float sum = 0.0f;
#pragma unroll
        for (int s = 0; s < 16; s++) {
            e[s] = __expf(e[s] - m);
            sum += e[s];
        }
        sum += __shfl_xor_sync(0xffffffffu, sum, 1);
        sum += __shfl_xor_sync(0xffffffffu, sum, 2);
        float inv = 1.0f / sum;
#pragma unroll
        for (int s = 0; s < 16; s++)
            pT[s * 4 + q][r] = e[s] * inv;
    }
    __syncthreads();

    {
        const int tc  = (t >> 4) * 2;
        const int ti2 = (t & 15) * 4;
        float oacc[2][4];
#pragma unroll
        for (int cc = 0; cc < 2; cc++)
#pragma unroll
            for (int i = 0; i < 4; i++) oacc[cc][i] = 0.0f;

#pragma unroll 4
        for (int j0 = 0; j0 < NT; j0 += 4) {
            float4 v0 = *(const float4*)(&vs[tc + 0][j0]);
            float4 v1 = *(const float4*)(&vs[tc + 1][j0]);
            float va0[4] = {v0.x, v0.y, v0.z, v0.w};
            float va1[4] = {v1.x, v1.y, v1.z, v1.w};
#pragma unroll
            for (int jj = 0; jj < 4; jj++) {
                float4 p4 = *(const float4*)(&pT[j0 + jj][ti2]);
                float p[4] = {p4.x, p4.y, p4.z, p4.w};
#pragma unroll
                for (int i = 0; i < 4; i++) {
                    oacc[0][i] += va0[jj] * p[i];
                    oacc[1][i] += va1[jj] * p[i];
                }
            }
        }
#pragma unroll
        for (int cc = 0; cc < 2; cc++) {
#pragma unroll
            for (int i = 0; i < 4; i++) {
                int tok = ti2 + i;
                int r   = tok >> 3;
                int col = tok & 7;
                O[base + (size_t)(tc + cc) * HW + (size_t)r * W_DIM + col] = oacc[cc][i];
            }
        }
    }
}

// ---------------------------------------------------------------------------
extern "C" void kernel_launch(void* const* d_in, const int* in_sizes, int n_in,
                              void* d_out, int out_size) {
    const float* x  = (const float*)d_in[0];
    const float* Wq = (const float*)d_in[1];
    const float* Wk = (const float*)d_in[2];
    const float* Wv = (const float*)d_in[3];
    const float* Wo = (const float*)d_in[4];
    float* out = (float*)d_out;

    void *pq, *pk, *pv;
    cudaGetSymbolAddress(&pq, g_q);
    cudaGetSymbolAddress(&pk, g_k);
    cudaGetSymbolAddress(&pv, g_v);
    float* q = (float*)pq;
    float* k = (float*)pk;
    float* v = (float*)pv;

    dim3 gproj(HW / 128, C_DIM / 128, BATCH);   // (512, 2, 4)
    proj_mma<<<gproj, 256>>>(Wq, x, q);
    proj_mma<<<gproj, 256>>>(Wk, x, k);
    proj_mma<<<gproj, 256>>>(Wv, x, v);

    dim3 gattn(NWH * NWW, HEADS, BATCH);        // (1024, 8, 4)
    attn_kernel<<<gattn, 256>>>(q, k, v, /*O overwrites q in-place*/ q);

    proj_mma<<<gproj, 256>>>(Wo, q, out);
}

// round 11
// speedup vs baseline: 1.6289x; 1.3114x over previous
#include <cuda_runtime.h>
#include <cuda_bf16.h>
#include <math.h>
#include <stdint.h>

typedef unsigned short ushort_t;

// Problem constants (B=4, C=256, H=W=256, heads=8, hd=32, WS=8 -> no padding)
#define BATCH   4
#define C_DIM   256
#define H_DIM   256
#define W_DIM   256
#define HW      (H_DIM * W_DIM)        // 65536
#define HEADS   8
#define HD      32
#define WSZ     8
#define NT      64
#define NWH     (H_DIM / WSZ)
#define NWW     (W_DIM / WSZ)

// Scratch
__device__ float   g_q[(size_t)BATCH * C_DIM * HW];
__device__ float   g_k[(size_t)BATCH * C_DIM * HW];
__device__ float   g_v[(size_t)BATCH * C_DIM * HW];
__device__ ushort_t g_xh[(size_t)BATCH * C_DIM * HW];   // bf16 hi, layout == x
__device__ ushort_t g_xl[(size_t)BATCH * C_DIM * HW];   // bf16 lo
__device__ ushort_t g_wh[4 * C_DIM * C_DIM];            // W bf16 hi [w][m][k]
__device__ ushort_t g_wl[4 * C_DIM * C_DIM];            // W bf16 lo

// ============================ helpers ======================================
__device__ __forceinline__ uint32_t smem_u32(const void* p) {
    uint32_t a;
    asm("{ .reg .u64 t; cvta.to.shared.u64 t, %1; cvt.u32.u64 %0, t; }"
        : "=r"(a) : "l"(p));
    return a;
}
__device__ __forceinline__ void ldsm4(uint32_t* r, uint32_t addr) {
    asm volatile("ldmatrix.sync.aligned.m8n8.x4.shared.b16 {%0,%1,%2,%3}, [%4];"
                 : "=r"(r[0]), "=r"(r[1]), "=r"(r[2]), "=r"(r[3]) : "r"(addr));
}
__device__ __forceinline__ void mma16816(float* c, const uint32_t* a,
                                         const uint32_t* b) {
    asm volatile(
        "mma.sync.aligned.m16n8k16.row.col.f32.bf16.bf16.f32 "
        "{%0,%1,%2,%3},{%4,%5,%6,%7},{%8,%9},{%0,%1,%2,%3};"
        : "+f"(c[0]), "+f"(c[1]), "+f"(c[2]), "+f"(c[3])
        : "r"(a[0]), "r"(a[1]), "r"(a[2]), "r"(a[3]), "r"(b[0]), "r"(b[1]));
}
// Packed pair convert: r = {bf16(b) : bf16(a)} (a in low half).
__device__ __forceinline__ uint32_t cvt2(float a, float b) {
    uint32_t r;
    asm("cvt.rn.bf16x2.f32 %0, %1, %2;" : "=r"(r) : "f"(b), "f"(a));
    return r;
}
// Split a float4 into hi-pair/lo-pair packed bf16x2 words.
__device__ __forceinline__ void split4(float4 v, uint2& hi, uint2& lo) {
    uint32_t h0 = cvt2(v.x, v.y);
    uint32_t h1 = cvt2(v.z, v.w);
    float fx = __uint_as_float(h0 << 16);
    float fy = __uint_as_float(h0 & 0xFFFF0000u);
    float fz = __uint_as_float(h1 << 16);
    float fw = __uint_as_float(h1 & 0xFFFF0000u);
    hi = make_uint2(h0, h1);
    lo = make_uint2(cvt2(v.x - fx, v.y - fy), cvt2(v.z - fz, v.w - fw));
}

// ---------------------------------------------------------------------------
// convert_w: 4 weight matrices fp32 [m][k] -> bf16 hi/lo, same layout.
// grid = (16, 4); block handles 4096 elements of weight blockIdx.y.
// ---------------------------------------------------------------------------
__global__ void convert_w(const float* __restrict__ W0, const float* __restrict__ W1,
                          const float* __restrict__ W2, const float* __restrict__ W3,
                          ushort_t* __restrict__ Oh, ushort_t* __restrict__ Ol) {
    const int w = blockIdx.y;
    const float* Ws = (w == 0) ? W0 : (w == 1) ? W1 : (w == 2) ? W2 : W3;
    ushort_t* oh = Oh + (size_t)w * C_DIM * C_DIM;
    ushort_t* ol = Ol + (size_t)w * C_DIM * C_DIM;
    const int t = threadIdx.x;
#pragma unroll
    for (int u = 0; u < 4; u++) {
        int fidx = blockIdx.x * 1024 + t + u * 256;   // float4 index
        float4 v = *(const float4*)(Ws + (size_t)fidx * 4);
        uint2 hi, lo;
        split4(v, hi, lo);
        *(uint2*)(oh + (size_t)fidx * 4) = hi;
        *(uint2*)(ol + (size_t)fidx * 4) = lo;
    }
}

// ---------------------------------------------------------------------------
// convert_x: streaming fp32 -> bf16 hi/lo, identical linear layout.
// grid = (4096); each thread converts 16 float4 (total = BATCH*C*HW floats).
// ---------------------------------------------------------------------------
__global__ void convert_x(const float* __restrict__ S,
                          ushort_t* __restrict__ Oh, ushort_t* __restrict__ Ol) {
    const size_t base = (size_t)blockIdx.x * 4096 + threadIdx.x;
#pragma unroll
    for (int u = 0; u < 16; u++) {
        size_t fidx = base + (size_t)u * 256;
        float4 v = *(const float4*)(S + fidx * 4);
        uint2 hi, lo;
        split4(v, hi, lo);
        *(uint2*)(Oh + fidx * 4) = hi;
        *(uint2*)(Ol + fidx * 4) = lo;
    }
}

// ---------------------------------------------------------------------------
// Tensor-core projection GEMM (mma.sync bf16 2-term split, preconverted ops):
//   Out[b][m][n] = sum_k W[m][k] * X[b][k][n]
// BM=128, BN=128, BK=32; 8 warps (2m x 4n), warp tile 64x32.
// A: g_wh/g_wl [m][k] bf16 -> uint4 copy into smem rows (ROWB=80 pad).
// B: g_xh/g_xl [k][n] bf16 -> k-pair packed transpose fill (coalesced 2B LDG).
// grid = (HW/128 = 512, C/128 = 2, BATCH)
// ---------------------------------------------------------------------------
#define ROWB 80

__global__ __launch_bounds__(256)
void proj_mma(const ushort_t* __restrict__ Ah, const ushort_t* __restrict__ Al,
              const ushort_t* __restrict__ Xh, const ushort_t* __restrict__ Xl,
              float* __restrict__ Out) {
    __shared__ __align__(16) char As_hi[128 * ROWB];
    __shared__ __align__(16) char As_lo[128 * ROWB];
    __shared__ __align__(16) char Bs_hi[128 * ROWB];
    __shared__ __align__(16) char Bs_lo[128 * ROWB];

    const int t   = threadIdx.x;
    const int l   = t & 31;
    const int wid = t >> 5;
    const int b   = blockIdx.z;
    const int n0  = blockIdx.x * 128;
    const int m0  = blockIdx.y * 128;
    const ushort_t* Xhb = Xh + (size_t)b * C_DIM * HW;
    const ushort_t* Xlb = Xl + (size_t)b * C_DIM * HW;
    float*          Ob  = Out + (size_t)b * C_DIM * HW;

    const int wm = (wid >> 2) * 64;
    const int wn = (wid & 3) * 32;

    const uint32_t asHi = smem_u32(As_hi), asLo = smem_u32(As_lo);
    const uint32_t bsHi = smem_u32(Bs_hi), bsLo = smem_u32(Bs_lo);

    const uint32_t aRow = (uint32_t)((l & 7) + ((l >> 3) & 1) * 8);
    const uint32_t aKof = (uint32_t)(((l >> 4) & 1) * 8);
    const uint32_t bRow = (uint32_t)((l & 7) + ((l >> 4) & 1) * 8);
    const uint32_t bKof = (uint32_t)(((l >> 3) & 1) * 8);

    float acc[4][4][4];
#pragma unroll
    for (int mi = 0; mi < 4; mi++)
#pragma unroll
        for (int ni = 0; ni < 4; ni++)
#pragma unroll
            for (int r = 0; r < 4; r++) acc[mi][ni][r] = 0.0f;

    for (int k0 = 0; k0 < C_DIM; k0 += 32) {
        __syncthreads();
        // ---- A fill: pure uint4 copy, [m][k] bf16 ----
#pragma unroll
        for (int i = 0; i < 2; i++) {
            int idx = t + i * 256;            // 0..511
            int m   = idx >> 2;               // 0..127
            int kq  = idx & 3;                // 8-k groups
            size_t go = (size_t)(m0 + m) * C_DIM + k0 + kq * 8;
            *(uint4*)(As_hi + m * ROWB + kq * 16) = *(const uint4*)(Ah + go);
            *(uint4*)(As_lo + m * ROWB + kq * 16) = *(const uint4*)(Al + go);
        }
        // ---- B fill: k-pair packed transpose from [k][n] bf16 ----
#pragma unroll
        for (int i = 0; i < 8; i++) {
            int idx = t + i * 256;            // 0..2047
            int n   = idx & 127;
            int kp  = idx >> 7;               // 0..15
            size_t go = (size_t)(k0 + 2 * kp) * HW + n0 + n;
            uint32_t hv = (uint32_t)Xhb[go] | ((uint32_t)Xhb[go + HW] << 16);
            uint32_t lv = (uint32_t)Xlb[go] | ((uint32_t)Xlb[go + HW] << 16);
            *(uint32_t*)(Bs_hi + n * ROWB + kp * 4) = hv;
            *(uint32_t*)(Bs_lo + n * ROWB + kp * 4) = lv;
        }
        __syncthreads();

        // ---- Compute: 2 k-steps of 16 (layouts verified @rel_err 9e-6) ----
#pragma unroll
        for (int ks = 0; ks < 2; ks++) {
            const uint32_t kk = (uint32_t)(ks * 16);
            uint32_t a_hi[4][4], a_lo[4][4], b_hi[4][2], b_lo[4][2];
#pragma unroll
            for (int mi = 0; mi < 4; mi++) {
                uint32_t ao = (uint32_t)((wm + mi * 16 + aRow) * ROWB)
                            + (kk + aKof) * 2;
                ldsm4(a_hi[mi], asHi + ao);
                ldsm4(a_lo[mi], asLo + ao);
            }
#pragma unroll
            for (int nj = 0; nj < 2; nj++) {
                uint32_t bo = (uint32_t)((wn + nj * 16 + bRow) * ROWB)
                            + (kk + bKof) * 2;
                uint32_t rh[4], rl[4];
                ldsm4(rh, bsHi + bo);
                ldsm4(rl, bsLo + bo);
                b_hi[nj * 2 + 0][0] = rh[0]; b_hi[nj * 2 + 0][1] = rh[1];
                b_hi[nj * 2 + 1][0] = rh[2]; b_hi[nj * 2 + 1][1] = rh[3];
                b_lo[nj * 2 + 0][0] = rl[0]; b_lo[nj * 2 + 0][1] = rl[1];
                b_lo[nj * 2 + 1][0] = rl[2]; b_lo[nj * 2 + 1][1] = rl[3];
            }
#pragma unroll
            for (int mi = 0; mi < 4; mi++)
#pragma unroll
                for (int ni = 0; ni < 4; ni++) {
                    mma16816(acc[mi][ni], a_hi[mi], b_hi[ni]);
                    mma16816(acc[mi][ni], a_hi[mi], b_lo[ni]);
                    mma16816(acc[mi][ni], a_lo[mi], b_hi[ni]);
                }
        }
    }

    // ---- Epilogue ----
    const int g  = l >> 2;
    const int tt = l & 3;
#pragma unroll
    for (int mi = 0; mi < 4; mi++) {
#pragma unroll
        for (int ni = 0; ni < 4; ni++) {
            const float* c = acc[mi][ni];
            int m = m0 + wm + mi * 16 + g;
            int n = n0 + wn + ni * 8 + tt * 2;
            *(float2*)(Ob + (size_t)m * HW + n)       = make_float2(c[0], c[1]);
            *(float2*)(Ob + (size_t)(m + 8) * HW + n) = make_float2(c[2], c[3]);
        }
    }
}

// ---------------------------------------------------------------------------
// Window attention (unchanged, measured 849us): one block per (window, head).
// ---------------------------------------------------------------------------
#define PT_PAD 4

__global__ __launch_bounds__(256)
void attn_kernel(const float* __restrict__ Q, const float* __restrict__ K,
                 const float* __restrict__ V, float* __restrict__ O) {
    __shared__ float qs[HD][NT];
    __shared__ float ks[HD][NT];
    __shared__ float vs[HD][NT];
    __shared__ float pT[NT][NT + PT_PAD];

    const int win  = blockIdx.x;
    const int wh   = win >> 5;
    const int ww   = win & 31;
    const int head = blockIdx.y;
    const int b    = blockIdx.z;
    const int t    = threadIdx.x;

    const size_t base = ((size_t)(b * C_DIM + head * HD)) * HW
                      + (size_t)(wh * WSZ) * W_DIM + (size_t)(ww * WSZ);

#pragma unroll
    for (int l = 0; l < 2; l++) {
        int idx4 = t + l * 256;
        int c    = idx4 >> 4;
        int tok  = (idx4 & 15) * 4;
        int r    = tok >> 3;
        int col  = tok & 7;
        size_t g = base + (size_t)c * HW + (size_t)r * W_DIM + col;
        *(float4*)(&qs[c][tok]) = *(const float4*)(Q + g);
        *(float4*)(&ks[c][tok]) = *(const float4*)(K + g);
        *(float4*)(&vs[c][tok]) = *(const float4*)(V + g);
    }
    __syncthreads();

    {
        const int ti = (t >> 4) * 4;
        const int tj = (t & 15) * 4;
        float sacc[4][4];
#pragma unroll
        for (int i = 0; i < 4; i++)
#pragma unroll
            for (int j = 0; j < 4; j++) sacc[i][j] = 0.0f;

#pragma unroll
        for (int c = 0; c < HD; c++) {
            float4 qa = *(const float4*)(&qs[c][ti]);
            float4 kb = *(const float4*)(&ks[c][tj]);
            float a[4] = {qa.x, qa.y, qa.z, qa.w};
            float bb[4] = {kb.x, kb.y, kb.z, kb.w};
#pragma unroll
            for (int i = 0; i < 4; i++)
#pragma unroll
                for (int j = 0; j < 4; j++)
                    sacc[i][j] += a[i] * bb[j];
        }
#pragma unroll
        for (int j = 0; j < 4; j++) {
            float4 row = make_float4(sacc[0][j], sacc[1][j], sacc[2][j], sacc[3][j]);
            *(float4*)(&pT[tj + j][ti]) = row;
        }
    }
    __syncthreads();

    {
        const float scale = 1.0f / sqrtf((float)HD);
        const int r = t >> 2;
        const int q = t & 3;
        float e[16];
        float m = -1e30f;
#pragma unroll
        for (int s = 0; s < 16; s++) {
            float xv = pT[s * 4 + q][r] * scale;
            e[s] = xv;
            m = fmaxf(m, xv);
        }
        m = fmaxf(m, __shfl_xor_sync(0xffffffffu, m, 1));
        m = fmaxf(m, __shfl_xor_sync(0xffffffffu, m, 2));
        float sum = 0.0f;
#pragma unroll
        for (int s = 0; s < 16; s++) {
            e[s] = __expf(e[s] - m);
            sum += e[s];
        }
        sum += __shfl_xor_sync(0xffffffffu, sum, 1);
        sum += __shfl_xor_sync(0xffffffffu, sum, 2);
        float inv = 1.0f / sum;
#pragma unroll
        for (int s = 0; s < 16; s++)
            pT[s * 4 + q][r] = e[s] * inv;
    }
    __syncthreads();

    {
        const int tc  = (t >> 4) * 2;
        const int ti2 = (t & 15) * 4;
        float oacc[2][4];
#pragma unroll
        for (int cc = 0; cc < 2; cc++)
#pragma unroll
            for (int i = 0; i < 4; i++) oacc[cc][i] = 0.0f;

#pragma unroll 4
        for (int j0 = 0; j0 < NT; j0 += 4) {
            float4 v0 = *(const float4*)(&vs[tc + 0][j0]);
            float4 v1 = *(const float4*)(&vs[tc + 1][j0]);
            float va0[4] = {v0.x, v0.y, v0.z, v0.w};
            float va1[4] = {v1.x, v1.y, v1.z, v1.w};
#pragma unroll
            for (int jj = 0; jj < 4; jj++) {
                float4 p4 = *(const float4*)(&pT[j0 + jj][ti2]);
                float p[4] = {p4.x, p4.y, p4.z, p4.w};
#pragma unroll
                for (int i = 0; i < 4; i++) {
                    oacc[0][i] += va0[jj] * p[i];
                    oacc[1][i] += va1[jj] * p[i];
                }
            }
        }
#pragma unroll
        for (int cc = 0; cc < 2; cc++) {
#pragma unroll
            for (int i = 0; i < 4; i++) {
                int tok = ti2 + i;
                int r   = tok >> 3;
                int col = tok & 7;
                O[base + (size_t)(tc + cc) * HW + (size_t)r * W_DIM + col] = oacc[cc][i];
            }
        }
    }
}

// ---------------------------------------------------------------------------
extern "C" void kernel_launch(void* const* d_in, const int* in_sizes, int n_in,
                              void* d_out, int out_size) {
    const float* x  = (const float*)d_in[0];
    const float* Wq = (const float*)d_in[1];
    const float* Wk = (const float*)d_in[2];
    const float* Wv = (const float*)d_in[3];
    const float* Wo = (const float*)d_in[4];
    float* out = (float*)d_out;

    void *pq, *pk, *pv, *pxh, *pxl, *pwh, *pwl;
    cudaGetSymbolAddress(&pq, g_q);
    cudaGetSymbolAddress(&pk, g_k);
    cudaGetSymbolAddress(&pv, g_v);
    cudaGetSymbolAddress(&pxh, g_xh);
    cudaGetSymbolAddress(&pxl, g_xl);
    cudaGetSymbolAddress(&pwh, g_wh);
    cudaGetSymbolAddress(&pwl, g_wl);
    float* q = (float*)pq;
    float* k = (float*)pk;
    float* v = (float*)pv;
    ushort_t* xh = (ushort_t*)pxh;
    ushort_t* xl = (ushort_t*)pxl;
    ushort_t* wh = (ushort_t*)pwh;
    ushort_t* wl = (ushort_t*)pwl;

    // Preconvert weights (all 4) and x.
    convert_w<<<dim3(16, 4), 256>>>(Wq, Wk, Wv, Wo, wh, wl);
    convert_x<<<4096, 256>>>(x, xh, xl);

    dim3 gproj(HW / 128, C_DIM / 128, BATCH);   // (512, 2, 4)
    proj_mma<<<gproj, 256>>>(wh + 0 * C_DIM * C_DIM, wl + 0 * C_DIM * C_DIM, xh, xl, q);
    proj_mma<<<gproj, 256>>>(wh + 1 * C_DIM * C_DIM, wl + 1 * C_DIM * C_DIM, xh, xl, k);
    proj_mma<<<gproj, 256>>>(wh + 2 * C_DIM * C_DIM, wl + 2 * C_DIM * C_DIM, xh, xl, v);

    dim3 gattn(NWH * NWW, HEADS, BATCH);        // (1024, 8, 4)
    attn_kernel<<<gattn, 256>>>(q, k, v, /*O overwrites q in-place*/ q);

    // Convert attention output, then final projection.
    convert_x<<<4096, 256>>>(q, xh, xl);
    proj_mma<<<gproj, 256>>>(wh + 3 * C_DIM * C_DIM, wl + 3 * C_DIM * C_DIM, xh, xl, out);
}